// round 5
// baseline (speedup 1.0000x reference)
#include <cuda_runtime.h>

constexpr int BATCH = 128;
constexpr int NODES = 8192;
constexpr int NI    = 6;
constexpr int NE    = 64;
constexpr int BB    = 8;      // batches per thread (table-reuse factor)
constexpr int TPB   = 256;

using u64 = unsigned long long;

__device__ __forceinline__ u64 pk2(float lo, float hi) {
    u64 r; asm("mov.b64 %0, {%1, %2};" : "=l"(r) : "f"(lo), "f"(hi)); return r;
}
__device__ __forceinline__ void upk2(u64 v, float& lo, float& hi) {
    asm("mov.b64 {%0, %1}, %2;" : "=f"(lo), "=f"(hi) : "l"(v));
}
__device__ __forceinline__ u64 fma2(u64 a, u64 b, u64 c) {
    u64 d; asm("fma.rn.f32x2 %0, %1, %2, %3;" : "=l"(d) : "l"(a), "l"(b), "l"(c)); return d;
}
__device__ __forceinline__ u64 mul2(u64 a, u64 b) {
    u64 d; asm("mul.rn.f32x2 %0, %1, %2;" : "=l"(d) : "l"(a), "l"(b)); return d;
}

// out[b,n] = sum_e tables[n,e] * prod_i (xi*bit_i(e) + (1-xi)*(1-bit_i(e)))
// == 6-D multilinear interpolation: fold table over bits 0..5 with lerps.
// Packing: P_j = (t[j], t[j+32]) packs along bit5 (folded last, scalar);
// bits 0..4 fold as packed f32x2 lerps. Level-0 base/diff precomputed per node.
__global__ void __launch_bounds__(TPB, 2)
lut_kernel(const float* __restrict__ x,
           const float* __restrict__ tables,
           float* __restrict__ out)
{
    const int n  = blockIdx.x * TPB + threadIdx.x;   // node (coalesced dim)
    const int b0 = blockIdx.y * BB;                  // first batch for this thread

    // ---- per-node setup: load 64-entry table row, build packed base/diff ----
    float t[NE];
    const float4* tp = reinterpret_cast<const float4*>(tables + (size_t)n * NE);
#pragma unroll
    for (int i = 0; i < NE / 4; i++) {
        float4 v = tp[i];
        t[4*i+0] = v.x; t[4*i+1] = v.y; t[4*i+2] = v.z; t[4*i+3] = v.w;
    }
    u64 A[16], D[16];   // level-0 lerp: W_m = A_m + x0 * D_m  (packed over bit5)
#pragma unroll
    for (int m = 0; m < 16; m++) {
        A[m] = pk2(t[2*m],               t[2*m+32]);
        D[m] = pk2(t[2*m+1] - t[2*m],    t[2*m+33] - t[2*m+32]);
    }

    const float* xp = x   + ((size_t)b0 * NODES + n) * NI;
    float*       op = out +  (size_t)b0 * NODES + n;

    // prefetch first batch's 6 inputs (24B, 8-byte aligned -> 3x LDG.64)
    float2 p0 = *reinterpret_cast<const float2*>(xp + 0);
    float2 p1 = *reinterpret_cast<const float2*>(xp + 2);
    float2 p2 = *reinterpret_cast<const float2*>(xp + 4);

#pragma unroll
    for (int bb = 0; bb < BB; bb++) {
        float xv[NI] = {p0.x, p0.y, p1.x, p1.y, p2.x, p2.y};
        if (bb + 1 < BB) {  // software-pipeline next batch's loads behind the fold
            const float* xn = xp + (size_t)(bb + 1) * NODES * NI;
            p0 = *reinterpret_cast<const float2*>(xn + 0);
            p1 = *reinterpret_cast<const float2*>(xn + 2);
            p2 = *reinterpret_cast<const float2*>(xn + 4);
        }

        float c[NI];
        u64 xx[NI], ox[NI];
#pragma unroll
        for (int i = 0; i < NI; i++) {
            c[i]  = __saturatef(xv[i]);        // clip(x, 0, 1)
            xx[i] = pk2(c[i], c[i]);
            ox[i] = pk2(1.0f - c[i], 1.0f - c[i]);
        }

        // level 0 (bit0): single packed FFMA each thanks to precomputed A/D
        u64 W[16];
#pragma unroll
        for (int m = 0; m < 16; m++) W[m] = fma2(xx[0], D[m], A[m]);

        // levels 1..4 (bits 1..4): packed lerp  W' = (1-xi)*W_even + xi*W_odd
#pragma unroll
        for (int lvl = 1; lvl < 5; lvl++) {
            const int cnt = 16 >> lvl;
#pragma unroll
            for (int m = 0; m < cnt; m++)
                W[m] = fma2(xx[lvl], W[2*m+1], mul2(ox[lvl], W[2*m]));
        }

        // level 5 (bit5): scalar lerp across the packed halves
        float lo, hi; upk2(W[0], lo, hi);
        op[(size_t)bb * NODES] = fmaf(c[5], hi, (1.0f - c[5]) * lo);
    }
}

extern "C" void kernel_launch(void* const* d_in, const int* in_sizes, int n_in,
                              void* d_out, int out_size)
{
    // metadata order: x [128,8192,6] f32, tables [8192,64] f32 (verify by size)
    const float* x;
    const float* tables;
    if (in_sizes[0] == BATCH * NODES * NI) {
        x = (const float*)d_in[0]; tables = (const float*)d_in[1];
    } else {
        x = (const float*)d_in[1]; tables = (const float*)d_in[0];
    }
    dim3 grid(NODES / TPB, BATCH / BB);
    lut_kernel<<<grid, TPB>>>(x, tables, (float*)d_out);
}

// round 7
// speedup vs baseline: 1.1281x; 1.1281x over previous
#include <cuda_runtime.h>
#include <cstdint>

constexpr int BATCH = 128;
constexpr int NODES = 8192;
constexpr int NI    = 6;
constexpr int NE    = 64;
constexpr int BB    = 8;      // batches per thread; also # of x slots (no reuse!)
constexpr int TPB   = 256;

constexpr int XSTAGE_FLOATS = TPB * NI;            // 1536 floats = 6144 B per batch-slot
constexpr int XSTAGE_BYTES  = XSTAGE_FLOATS * 4;
constexpr int SMEM_MBAR_OFF = 0;                    // BB x 8B barriers
constexpr int SMEM_X_OFF    = 64;
constexpr int SMEM_TBL_OFF  = SMEM_X_OFF + BB * XSTAGE_BYTES;   // 64 + 49152
constexpr int SMEM_BYTES    = SMEM_TBL_OFF + TPB * NE * 4;      // + 65536 = 114752 (occ 2)

using u64 = unsigned long long;

__device__ __forceinline__ u64 pk2(float lo, float hi) {
    u64 r; asm("mov.b64 %0, {%1, %2};" : "=l"(r) : "f"(lo), "f"(hi)); return r;
}
__device__ __forceinline__ void upk2(u64 v, float& lo, float& hi) {
    asm("mov.b64 {%0, %1}, %2;" : "=f"(lo), "=f"(hi) : "l"(v));
}
__device__ __forceinline__ u64 fma2(u64 a, u64 b, u64 c) {
    u64 d; asm("fma.rn.f32x2 %0, %1, %2, %3;" : "=l"(d) : "l"(a), "l"(b), "l"(c)); return d;
}
__device__ __forceinline__ u64 mul2(u64 a, u64 b) {
    u64 d; asm("mul.rn.f32x2 %0, %1, %2;" : "=l"(d) : "l"(a), "l"(b)); return d;
}
__device__ __forceinline__ uint32_t s2u(const void* p) {
    return (uint32_t)__cvta_generic_to_shared(p);
}
__device__ __forceinline__ void mbar_init(uint32_t a, uint32_t cnt) {
    asm volatile("mbarrier.init.shared.b64 [%0], %1;" :: "r"(a), "r"(cnt) : "memory");
}
__device__ __forceinline__ void mbar_expect_tx(uint32_t a, uint32_t bytes) {
    asm volatile("mbarrier.arrive.expect_tx.shared.b64 _, [%0], %1;" :: "r"(a), "r"(bytes) : "memory");
}
__device__ __forceinline__ void bulk_g2s(uint32_t dst, const void* src, uint32_t bytes, uint32_t bar) {
    asm volatile("cp.async.bulk.shared::cta.global.mbarrier::complete_tx::bytes [%0], [%1], %2, [%3];"
                 :: "r"(dst), "l"(src), "r"(bytes), "r"(bar) : "memory");
}
__device__ __forceinline__ void mbar_wait0(uint32_t a) {   // wait phase-0 completion
    asm volatile(
        "{\n\t.reg .pred P;\n"
        "W%=:\n\t"
        "mbarrier.try_wait.parity.acquire.cta.shared::cta.b64 P, [%0], 0, 0x989680;\n\t"
        "@P bra D%=;\n\t"
        "bra W%=;\n"
        "D%=:\n\t}"
        :: "r"(a) : "memory");
}

// out[b,n] = 6-D multilinear interp of tables[n,:] at clip(x[b,n,:], 0, 1).
// Fold table bit-by-bit; bit5 packed into f32x2 lanes, bits 0..4 packed lerps.
// All 8 batches' x prefetched into distinct smem slots up front (no slot reuse,
// no producer/consumer hazard). Table staged coalesced into smem with a +2*row
// word rotation so per-thread row reads are 2-way-conflict LDS.64 with static
// register indexing.
__global__ void __launch_bounds__(TPB, 2)
lut_kernel(const float* __restrict__ x,
           const float* __restrict__ tables,
           float* __restrict__ out)
{
    extern __shared__ unsigned char smem[];
    float*    xs  = (float*)(smem + SMEM_X_OFF);
    float*    tbl = (float*)(smem + SMEM_TBL_OFF);
    const uint32_t mbar0 = s2u(smem + SMEM_MBAR_OFF);
    const uint32_t xs0   = s2u(xs);

    const int tid = threadIdx.x;
    const int n0  = blockIdx.x * TPB;        // first node of this block
    const int b0  = blockIdx.y * BB;         // first batch of this block

    // ---- init one mbarrier per batch-slot; launch all BB copies up front ----
    if (tid == 0) {
        #pragma unroll
        for (int s = 0; s < BB; s++) mbar_init(mbar0 + 8u * s, 1);
    }
    __syncthreads();
    if (tid == 0) {
        #pragma unroll
        for (int s = 0; s < BB; s++) {
            const float* src = x + ((size_t)(b0 + s) * NODES + n0) * NI;  // 6144B, 16B-aligned
            mbar_expect_tx(mbar0 + 8u * s, XSTAGE_BYTES);
            bulk_g2s(xs0 + s * XSTAGE_BYTES, src, XSTAGE_BYTES, mbar0 + 8u * s);
        }
    }

    // ---- stage this block's 64KB table chunk, coalesced LDG -> rotated STS ----
    {
        const float4* tg = (const float4*)(tables + (size_t)n0 * NE);
        #pragma unroll
        for (int j = 0; j < (TPB * NE / 4) / TPB; j++) {    // 16 float4 per thread
            int i = tid + j * TPB;                          // coalesced gmem index
            float4 v = tg[i];
            int r  = i >> 4;                                // dest row (node within block)
            int c0 = (i & 15) * 4;                          // first word of this float4
            float w[4] = {v.x, v.y, v.z, v.w};
            #pragma unroll
            for (int k = 0; k < 4; k++)
                tbl[r * NE + ((c0 + k + 2 * r) & (NE - 1))] = w[k];
        }
    }
    __syncthreads();

    // ---- per-node: read own rotated row, build packed level-0 base/diff ----
    u64 A[16], D[16];   // level-0 lerp W_m = A_m + x0*D_m, packed over bit5: (m, m+16)
    {
        const float* tr = tbl + (size_t)tid * NE;
        const int rot = (2 * tid) & (NE - 1);               // even -> float2 pairs intact
        #pragma unroll
        for (int m = 0; m < 16; m++) {
            float2 lo = *(const float2*)(tr + ((2 * m      + rot) & (NE - 1)));
            float2 hi = *(const float2*)(tr + ((2 * m + 32 + rot) & (NE - 1)));
            A[m] = pk2(lo.x,        hi.x);
            D[m] = pk2(lo.y - lo.x, hi.y - hi.x);
        }
    }

    float* op = out + (size_t)b0 * NODES + n0 + tid;

    #pragma unroll
    for (int bb = 0; bb < BB; bb++) {
        mbar_wait0(mbar0 + 8u * bb);                        // slot written exactly once

        const float* xr = xs + bb * XSTAGE_FLOATS + tid * NI;
        float2 q0 = *(const float2*)(xr + 0);
        float2 q1 = *(const float2*)(xr + 2);
        float2 q2 = *(const float2*)(xr + 4);
        float xv[NI] = {q0.x, q0.y, q1.x, q1.y, q2.x, q2.y};

        float c[NI];
        u64 xx[5], ox[5];                                   // packed x / (1-x), levels 0..4
        #pragma unroll
        for (int i = 0; i < NI; i++) c[i] = __saturatef(xv[i]);
        #pragma unroll
        for (int i = 0; i < 5; i++) {
            xx[i] = pk2(c[i], c[i]);
            ox[i] = pk2(1.0f - c[i], 1.0f - c[i]);
        }

        // level 0 (bit0): one packed FFMA per pair (precomputed base/diff)
        u64 W[16];
        #pragma unroll
        for (int m = 0; m < 16; m++) W[m] = fma2(xx[0], D[m], A[m]);

        // levels 1..4 (bits 1..4): packed lerp  W' = (1-xi)*W_even + xi*W_odd
        #pragma unroll
        for (int lvl = 1; lvl < 5; lvl++) {
            const int cnt = 16 >> lvl;
            #pragma unroll
            for (int m = 0; m < cnt; m++)
                W[m] = fma2(xx[lvl], W[2*m+1], mul2(ox[lvl], W[2*m]));
        }

        // level 5 (bit5): scalar lerp across the packed halves
        float lo, hi; upk2(W[0], lo, hi);
        op[(size_t)bb * NODES] = fmaf(c[5], hi, (1.0f - c[5]) * lo);
    }
}

extern "C" void kernel_launch(void* const* d_in, const int* in_sizes, int n_in,
                              void* d_out, int out_size)
{
    const float* x;
    const float* tables;
    if (in_sizes[0] == BATCH * NODES * NI) {
        x = (const float*)d_in[0]; tables = (const float*)d_in[1];
    } else {
        x = (const float*)d_in[1]; tables = (const float*)d_in[0];
    }
    cudaFuncSetAttribute(lut_kernel, cudaFuncAttributeMaxDynamicSharedMemorySize, SMEM_BYTES);
    dim3 grid(NODES / TPB, BATCH / BB);
    lut_kernel<<<grid, TPB, SMEM_BYTES>>>(x, tables, (float*)d_out);
}

// round 8
// speedup vs baseline: 1.2996x; 1.1520x over previous
#include <cuda_runtime.h>
#include <cstdint>

constexpr int BATCH = 128;
constexpr int NODES = 8192;
constexpr int NI    = 6;
constexpr int NE    = 64;
constexpr int BB    = 16;     // batches per thread
constexpr int TPB   = 128;
constexpr int SLOTS = 8;      // x-ring depth (each slot used exactly twice)

constexpr int XSTAGE_FLOATS = TPB * NI;            // 768 floats = 3072 B per batch-slot
constexpr int XSTAGE_BYTES  = XSTAGE_FLOATS * 4;
constexpr int SMEM_MBAR_OFF = 0;                    // 8 x (full,empty) pairs, 16B each
constexpr int SMEM_X_OFF    = 256;
constexpr int SMEM_TBL_OFF  = SMEM_X_OFF + SLOTS * XSTAGE_BYTES;   // 256 + 24576
constexpr int SMEM_BYTES    = SMEM_TBL_OFF + TPB * NE * 4;         // + 32768 = 57600 (occ 4)

using u64 = unsigned long long;

__device__ __forceinline__ u64 pk2(float lo, float hi) {
    u64 r; asm("mov.b64 %0, {%1, %2};" : "=l"(r) : "f"(lo), "f"(hi)); return r;
}
__device__ __forceinline__ void upk2(u64 v, float& lo, float& hi) {
    asm("mov.b64 {%0, %1}, %2;" : "=f"(lo), "=f"(hi) : "l"(v));
}
__device__ __forceinline__ u64 fma2(u64 a, u64 b, u64 c) {
    u64 d; asm("fma.rn.f32x2 %0, %1, %2, %3;" : "=l"(d) : "l"(a), "l"(b), "l"(c)); return d;
}
__device__ __forceinline__ u64 sub2(u64 a, u64 b) {
    u64 d; asm("sub.rn.f32x2 %0, %1, %2;" : "=l"(d) : "l"(a), "l"(b)); return d;
}
__device__ __forceinline__ uint32_t s2u(const void* p) {
    return (uint32_t)__cvta_generic_to_shared(p);
}
__device__ __forceinline__ void mbar_init(uint32_t a, uint32_t cnt) {
    asm volatile("mbarrier.init.shared.b64 [%0], %1;" :: "r"(a), "r"(cnt) : "memory");
}
__device__ __forceinline__ void mbar_expect_tx(uint32_t a, uint32_t bytes) {
    asm volatile("mbarrier.arrive.expect_tx.shared.b64 _, [%0], %1;" :: "r"(a), "r"(bytes) : "memory");
}
__device__ __forceinline__ void mbar_arrive(uint32_t a) {   // release: orders prior accesses
    asm volatile("mbarrier.arrive.release.cta.shared::cta.b64 _, [%0];" :: "r"(a) : "memory");
}
__device__ __forceinline__ void bulk_g2s(uint32_t dst, const void* src, uint32_t bytes, uint32_t bar) {
    asm volatile("cp.async.bulk.shared::cta.global.mbarrier::complete_tx::bytes [%0], [%1], %2, [%3];"
                 :: "r"(dst), "l"(src), "r"(bytes), "r"(bar) : "memory");
}
__device__ __forceinline__ void mbar_wait(uint32_t a, uint32_t parity) {   // acquire
    asm volatile(
        "{\n\t.reg .pred P;\n"
        "W%=:\n\t"
        "mbarrier.try_wait.parity.acquire.cta.shared::cta.b64 P, [%0], %1, 0x989680;\n\t"
        "@P bra D%=;\n\t"
        "bra W%=;\n"
        "D%=:\n\t}"
        :: "r"(a), "r"(parity) : "memory");
}

// out[b,n] = 6-D multilinear interp of tables[n,:] at clip(x[b,n,:], 0, 1).
// Bits 0,1 folded into per-node quad coefficients (a + x0 b + x1 c + x0x1 d),
// bits 2..4 as packed difference-form lerps, bit 5 packed in f32x2 lanes.
// x streamed via cp.async.bulk into an 8-slot ring; each slot reused exactly
// once via canonical full/empty mbarrier pairs (empty arrive at END of batch).
__global__ void __launch_bounds__(TPB, 4)
lut_kernel(const float* __restrict__ x,
           const float* __restrict__ tables,
           float* __restrict__ out)
{
    extern __shared__ unsigned char smem[];
    float*    xs  = (float*)(smem + SMEM_X_OFF);
    float*    tbl = (float*)(smem + SMEM_TBL_OFF);
    const uint32_t mb  = s2u(smem + SMEM_MBAR_OFF);   // full[s]=mb+16s, empty[s]=mb+16s+8
    const uint32_t xs0 = s2u(xs);

    const int tid = threadIdx.x;
    const int n0  = blockIdx.x * TPB;        // first node of this block
    const int b0  = blockIdx.y * BB;         // first batch of this block

    if (tid == 0) {
        #pragma unroll
        for (int s = 0; s < SLOTS; s++) {
            mbar_init(mb + 16u * s,     1);      // full: tx-based
            mbar_init(mb + 16u * s + 8, TPB);    // empty: all threads arrive
        }
    }
    __syncthreads();
    if (tid == 0) {                               // fill the whole ring up front
        #pragma unroll
        for (int s = 0; s < SLOTS; s++) {
            const float* src = x + ((size_t)(b0 + s) * NODES + n0) * NI;  // 3072B, 16B-aligned
            mbar_expect_tx(mb + 16u * s, XSTAGE_BYTES);
            bulk_g2s(xs0 + s * XSTAGE_BYTES, src, XSTAGE_BYTES, mb + 16u * s);
        }
    }

    // ---- stage this block's 32KB table chunk: coalesced LDG -> +2*row-rotated STS.64 ----
    {
        const float4* tg = (const float4*)(tables + (size_t)n0 * NE);
        #pragma unroll
        for (int j = 0; j < (TPB * NE / 4) / TPB; j++) {    // 16 float4 per thread
            int i = tid + j * TPB;                          // coalesced gmem index
            float4 v = tg[i];
            int r  = i >> 4;                                // dest row
            int c0 = (i & 15) * 4;                          // first word (even)
            float* row = tbl + r * NE;
            int w0 = (c0     + 2 * r) & (NE - 1);           // even -> 8B aligned
            int w1 = (c0 + 2 + 2 * r) & (NE - 1);
            *(float2*)(row + w0) = make_float2(v.x, v.y);
            *(float2*)(row + w1) = make_float2(v.z, v.w);
        }
    }
    __syncthreads();

    // ---- per-node: build packed quad coefficients over bits 0,1 (x bit5 pairing) ----
    // quad m covers entries 4m..4m+3 (lo) and 4m+32..4m+35 (hi):
    //   val = a + x0*b + x1*c + x0*x1*d
    u64 Aq[8], Bq[8], Cq[8], Dq[8];
    {
        const float* tr = tbl + (size_t)tid * NE;
        const int rot = (2 * tid) & (NE - 1);               // even: float2 pairs intact
        #pragma unroll
        for (int m = 0; m < 8; m++) {
            float2 l01 = *(const float2*)(tr + ((4*m      + rot) & (NE - 1)));
            float2 l23 = *(const float2*)(tr + ((4*m + 2  + rot) & (NE - 1)));
            float2 h01 = *(const float2*)(tr + ((4*m + 32 + rot) & (NE - 1)));
            float2 h23 = *(const float2*)(tr + ((4*m + 34 + rot) & (NE - 1)));
            float lb = l01.y - l01.x, hb = h01.y - h01.x;
            Aq[m] = pk2(l01.x, h01.x);
            Bq[m] = pk2(lb, hb);
            Cq[m] = pk2(l23.x - l01.x, h23.x - h01.x);
            Dq[m] = pk2((l23.y - l23.x) - lb, (h23.y - h23.x) - hb);
        }
    }

    float* op = out + (size_t)b0 * NODES + n0 + tid;

    #pragma unroll
    for (int bb = 0; bb < BB; bb++) {
        const int s = bb & (SLOTS - 1);
        mbar_wait(mb + 16u * s, (bb >> 3) & 1);             // full[s], acquire

        const float* xr = xs + s * XSTAGE_FLOATS + tid * NI;
        float2 q0 = *(const float2*)(xr + 0);
        float2 q1 = *(const float2*)(xr + 2);
        float2 q2 = *(const float2*)(xr + 4);

        float c0 = __saturatef(q0.x), c1 = __saturatef(q0.y);
        float c2 = __saturatef(q1.x), c3 = __saturatef(q1.y);
        float c4 = __saturatef(q2.x), c5 = __saturatef(q2.y);
        float c01 = c0 * c1;
        u64 x0  = pk2(c0,  c0),  x1 = pk2(c1, c1), x01 = pk2(c01, c01);
        u64 x2  = pk2(c2,  c2),  x3 = pk2(c3, c3), x4  = pk2(c4, c4);

        // bits 0,1: 3 FFMA2 per quad, 8 independent chains
        u64 W[8];
        #pragma unroll
        for (int m = 0; m < 8; m++)
            W[m] = fma2(x01, Dq[m], fma2(x1, Cq[m], fma2(x0, Bq[m], Aq[m])));

        // bits 2..4: packed difference-form lerps
        #pragma unroll
        for (int m = 0; m < 4; m++) W[m] = fma2(x2, sub2(W[2*m+1], W[2*m]), W[2*m]);
        #pragma unroll
        for (int m = 0; m < 2; m++) W[m] = fma2(x3, sub2(W[2*m+1], W[2*m]), W[2*m]);
        W[0] = fma2(x4, sub2(W[1], W[0]), W[0]);

        // bit 5: scalar difference-form lerp across the packed halves
        float lo, hi; upk2(W[0], lo, hi);
        op[(size_t)bb * NODES] = fmaf(c5, hi - lo, lo);

        // release slot s: all reads of xs[s] are architecturally complete here
        mbar_arrive(mb + 16u * s + 8);                      // empty[s], release

        if (tid == 0 && bb < BB - SLOTS) {                  // re-arm slot for batch bb+8
            mbar_wait(mb + 16u * s + 8, 0);                 // wait all 128 empty-arrives
            const float* src = x + ((size_t)(b0 + bb + SLOTS) * NODES + n0) * NI;
            mbar_expect_tx(mb + 16u * s, XSTAGE_BYTES);
            bulk_g2s(xs0 + s * XSTAGE_BYTES, src, XSTAGE_BYTES, mb + 16u * s);
        }
    }
}

extern "C" void kernel_launch(void* const* d_in, const int* in_sizes, int n_in,
                              void* d_out, int out_size)
{
    const float* x;
    const float* tables;
    if (in_sizes[0] == BATCH * NODES * NI) {
        x = (const float*)d_in[0]; tables = (const float*)d_in[1];
    } else {
        x = (const float*)d_in[1]; tables = (const float*)d_in[0];
    }
    cudaFuncSetAttribute(lut_kernel, cudaFuncAttributeMaxDynamicSharedMemorySize, SMEM_BYTES);
    dim3 grid(NODES / TPB, BATCH / BB);
    lut_kernel<<<grid, TPB, SMEM_BYTES>>>(x, tables, (float*)d_out);
}

// round 9
// speedup vs baseline: 1.4496x; 1.1155x over previous
#include <cuda_runtime.h>
#include <cstdint>

constexpr int BATCH = 128;
constexpr int NODES = 8192;
constexpr int NI    = 6;
constexpr int NE    = 64;
constexpr int BB    = 16;     // batches per thread = # of x slots (each written once)
constexpr int TPB   = 128;

constexpr int XSTAGE_FLOATS = TPB * NI;            // 768 floats = 3072 B per batch-slot
constexpr int XSTAGE_BYTES  = XSTAGE_FLOATS * 4;
constexpr int SMEM_MBAR_OFF = 0;                    // 16 x 8B full-barriers
constexpr int SMEM_X_OFF    = 256;                  // slots 0..15: [256, 49408)
// Table OVERLAYS slots 8..15: it is only live during the prologue (coeff build),
// and slots 8..15 are filled only after the post-build __syncthreads().
constexpr int SMEM_TBL_OFF  = SMEM_X_OFF + 8 * XSTAGE_BYTES;    // 24832
constexpr int SMEM_BYTES    = SMEM_TBL_OFF + TPB * NE * 4;      // 57600 -> occ 4

using u64 = unsigned long long;

__device__ __forceinline__ u64 pk2(float lo, float hi) {
    u64 r; asm("mov.b64 %0, {%1, %2};" : "=l"(r) : "f"(lo), "f"(hi)); return r;
}
__device__ __forceinline__ void upk2(u64 v, float& lo, float& hi) {
    asm("mov.b64 {%0, %1}, %2;" : "=f"(lo), "=f"(hi) : "l"(v));
}
__device__ __forceinline__ u64 fma2(u64 a, u64 b, u64 c) {
    u64 d; asm("fma.rn.f32x2 %0, %1, %2, %3;" : "=l"(d) : "l"(a), "l"(b), "l"(c)); return d;
}
__device__ __forceinline__ u64 sub2(u64 a, u64 b) {
    u64 d; asm("sub.rn.f32x2 %0, %1, %2;" : "=l"(d) : "l"(a), "l"(b)); return d;
}
__device__ __forceinline__ uint32_t s2u(const void* p) {
    return (uint32_t)__cvta_generic_to_shared(p);
}
__device__ __forceinline__ void mbar_init(uint32_t a, uint32_t cnt) {
    asm volatile("mbarrier.init.shared.b64 [%0], %1;" :: "r"(a), "r"(cnt) : "memory");
}
__device__ __forceinline__ void mbar_expect_tx(uint32_t a, uint32_t bytes) {
    asm volatile("mbarrier.arrive.expect_tx.shared.b64 _, [%0], %1;" :: "r"(a), "r"(bytes) : "memory");
}
__device__ __forceinline__ void bulk_g2s(uint32_t dst, const void* src, uint32_t bytes, uint32_t bar) {
    asm volatile("cp.async.bulk.shared::cta.global.mbarrier::complete_tx::bytes [%0], [%1], %2, [%3];"
                 :: "r"(dst), "l"(src), "r"(bytes), "r"(bar) : "memory");
}
__device__ __forceinline__ void mbar_wait0(uint32_t a) {   // acquire, phase 0 (slots written once)
    asm volatile(
        "{\n\t.reg .pred P;\n"
        "W%=:\n\t"
        "mbarrier.try_wait.parity.acquire.cta.shared::cta.b64 P, [%0], 0, 0x989680;\n\t"
        "@P bra D%=;\n\t"
        "bra W%=;\n"
        "D%=:\n\t}"
        :: "r"(a) : "memory");
}

// out[b,n] = 6-D multilinear interp of tables[n,:] at clip(x[b,n,:], 0, 1).
// Bits 0,1 folded into per-node quad coefficients (a + x0 b + x1 c + x0x1 d),
// bits 2..4 packed difference-form lerps, bit 5 packed across f32x2 lanes.
// All 16 batches' x prefetched into 16 dedicated slots (no slot reuse, no
// empty barriers); slots 8..15 overlay the table region, which is dead after
// the coefficient build.
__global__ void __launch_bounds__(TPB, 4)
lut_kernel(const float* __restrict__ x,
           const float* __restrict__ tables,
           float* __restrict__ out)
{
    extern __shared__ unsigned char smem[];
    float*    xs  = (float*)(smem + SMEM_X_OFF);
    float*    tbl = (float*)(smem + SMEM_TBL_OFF);
    const uint32_t mb  = s2u(smem + SMEM_MBAR_OFF);   // full[s] = mb + 8s
    const uint32_t xs0 = s2u(xs);

    const int tid = threadIdx.x;
    const int n0  = blockIdx.x * TPB;        // first node of this block
    const int b0  = blockIdx.y * BB;         // first batch of this block
    const float* xbase = x + ((size_t)b0 * NODES + n0) * NI;

    if (tid == 0) {
        #pragma unroll
        for (int s = 0; s < BB; s++) mbar_init(mb + 8u * s, 1);
    }
    __syncthreads();
    if (tid == 0) {                           // slots 0..7: disjoint from table region
        #pragma unroll
        for (int s = 0; s < 8; s++) {
            mbar_expect_tx(mb + 8u * s, XSTAGE_BYTES);
            bulk_g2s(xs0 + s * XSTAGE_BYTES, xbase + (size_t)s * NODES * NI,
                     XSTAGE_BYTES, mb + 8u * s);
        }
    }

    // ---- stage this block's 32KB table chunk: coalesced LDG -> +2*row-rotated STS.64 ----
    {
        const float4* tg = (const float4*)(tables + (size_t)n0 * NE);
        #pragma unroll
        for (int j = 0; j < (TPB * NE / 4) / TPB; j++) {    // 16 float4 per thread
            int i = tid + j * TPB;                          // coalesced gmem index
            float4 v = tg[i];
            int r  = i >> 4;                                // dest row
            int c0 = (i & 15) * 4;                          // first word (even)
            float* row = tbl + r * NE;
            int w0 = (c0     + 2 * r) & (NE - 1);           // even -> 8B aligned
            int w1 = (c0 + 2 + 2 * r) & (NE - 1);
            *(float2*)(row + w0) = make_float2(v.x, v.y);
            *(float2*)(row + w1) = make_float2(v.z, v.w);
        }
    }
    __syncthreads();

    // ---- per-node packed quad coefficients over bits 0,1 (pairing = bit 5) ----
    // quad m covers entries 4m..4m+3 (lane lo) and 4m+32..4m+35 (lane hi):
    //   val = a + x0*b + x1*c + x0*x1*d
    // Every LDS below is CONSUMED here (into Aq..Dq) before the next barrier,
    // so the overlay TMA writes issued after it cannot race these reads.
    u64 Aq[8], Bq[8], Cq[8], Dq[8];
    {
        const float* tr = tbl + (size_t)tid * NE;
        const int rot = (2 * tid) & (NE - 1);               // even: float2 pairs intact
        #pragma unroll
        for (int m = 0; m < 8; m++) {
            float2 l01 = *(const float2*)(tr + ((4*m      + rot) & (NE - 1)));
            float2 l23 = *(const float2*)(tr + ((4*m + 2  + rot) & (NE - 1)));
            float2 h01 = *(const float2*)(tr + ((4*m + 32 + rot) & (NE - 1)));
            float2 h23 = *(const float2*)(tr + ((4*m + 34 + rot) & (NE - 1)));
            float lb = l01.y - l01.x, hb = h01.y - h01.x;
            Aq[m] = pk2(l01.x, h01.x);
            Bq[m] = pk2(lb, hb);
            Cq[m] = pk2(l23.x - l01.x, h23.x - h01.x);
            Dq[m] = pk2((l23.y - l23.x) - lb, (h23.y - h23.x) - hb);
        }
    }
    __syncthreads();      // table now dead -> safe to overwrite with slots 8..15

    if (tid == 0) {
        #pragma unroll
        for (int s = 8; s < BB; s++) {
            mbar_expect_tx(mb + 8u * s, XSTAGE_BYTES);
            bulk_g2s(xs0 + s * XSTAGE_BYTES, xbase + (size_t)s * NODES * NI,
                     XSTAGE_BYTES, mb + 8u * s);
        }
    }

    // ---- mainloop: all addressing is base + compile-time immediate ----
    const float* xt = xs + tid * NI;                        // per-thread x base
    float*       op = out + (size_t)b0 * NODES + n0 + tid;  // per-thread out base

    #pragma unroll
    for (int bb = 0; bb < BB; bb++) {
        mbar_wait0(mb + 8u * bb);                           // slot written exactly once

        const float* xr = xt + bb * XSTAGE_FLOATS;          // immediate offset
        float2 q0 = *(const float2*)(xr + 0);
        float2 q1 = *(const float2*)(xr + 2);
        float2 q2 = *(const float2*)(xr + 4);

        float c0 = __saturatef(q0.x), c1 = __saturatef(q0.y);
        float c2 = __saturatef(q1.x), c3 = __saturatef(q1.y);
        float c4 = __saturatef(q2.x), c5 = __saturatef(q2.y);
        float c01 = c0 * c1;
        u64 x0  = pk2(c0,  c0), x1 = pk2(c1, c1), x01 = pk2(c01, c01);
        u64 x2  = pk2(c2,  c2), x3 = pk2(c3, c3), x4  = pk2(c4, c4);

        // bits 0,1: 3 FFMA2 per quad, 8 independent chains
        u64 W[8];
        #pragma unroll
        for (int m = 0; m < 8; m++)
            W[m] = fma2(x01, Dq[m], fma2(x1, Cq[m], fma2(x0, Bq[m], Aq[m])));

        // bits 2..4: packed difference-form lerps
        #pragma unroll
        for (int m = 0; m < 4; m++) W[m] = fma2(x2, sub2(W[2*m+1], W[2*m]), W[2*m]);
        #pragma unroll
        for (int m = 0; m < 2; m++) W[m] = fma2(x3, sub2(W[2*m+1], W[2*m]), W[2*m]);
        W[0] = fma2(x4, sub2(W[1], W[0]), W[0]);

        // bit 5: scalar difference-form lerp across the packed halves
        float lo, hi; upk2(W[0], lo, hi);
        op[bb * NODES] = fmaf(c5, hi - lo, lo);             // immediate-offset STG
    }
}

extern "C" void kernel_launch(void* const* d_in, const int* in_sizes, int n_in,
                              void* d_out, int out_size)
{
    const float* x;
    const float* tables;
    if (in_sizes[0] == BATCH * NODES * NI) {
        x = (const float*)d_in[0]; tables = (const float*)d_in[1];
    } else {
        x = (const float*)d_in[1]; tables = (const float*)d_in[0];
    }
    cudaFuncSetAttribute(lut_kernel, cudaFuncAttributeMaxDynamicSharedMemorySize, SMEM_BYTES);
    dim3 grid(NODES / TPB, BATCH / BB);
    lut_kernel<<<grid, TPB, SMEM_BYTES>>>(x, tables, (float*)d_out);
}

// round 10
// speedup vs baseline: 1.7507x; 1.2077x over previous
#include <cuda_runtime.h>
#include <cstdint>

constexpr int BATCH = 128;
constexpr int NODES = 8192;
constexpr int NI    = 6;
constexpr int NE    = 64;
constexpr int BB    = 16;     // batches per thread
constexpr int TPB   = 128;
constexpr int PF    = 3;      // x prefetch depth (batches in flight per thread)

using u64 = unsigned long long;

__device__ __forceinline__ u64 pk2(float lo, float hi) {
    u64 r; asm("mov.b64 %0, {%1, %2};" : "=l"(r) : "f"(lo), "f"(hi)); return r;
}
__device__ __forceinline__ void upk2(u64 v, float& lo, float& hi) {
    asm("mov.b64 {%0, %1}, %2;" : "=f"(lo), "=f"(hi) : "l"(v));
}
__device__ __forceinline__ u64 fma2(u64 a, u64 b, u64 c) {
    u64 d; asm("fma.rn.f32x2 %0, %1, %2, %3;" : "=l"(d) : "l"(a), "l"(b), "l"(c)); return d;
}
__device__ __forceinline__ u64 sub2(u64 a, u64 b) {
    u64 d; asm("sub.rn.f32x2 %0, %1, %2;" : "=l"(d) : "l"(a), "l"(b)); return d;
}

// out[b,n] = 6-D multilinear interp of tables[n,:] at clip(x[b,n,:], 0, 1).
// Bits 0,1 folded into per-node quad coefficients (a + x0 b + x1 c + x0x1 d),
// bits 2..4 packed difference-form lerps, bit 5 packed across f32x2 lanes.
// x is read by plain coalesced LDG with a depth-3 register prefetch pipeline
// (no smem ring, no mbarriers, no spin waits). Table staged once into smem
// (coalesced LDG -> +2*row rotated STS) and read once into registers.
__global__ void __launch_bounds__(TPB, 4)
lut_kernel(const float* __restrict__ x,
           const float* __restrict__ tables,
           float* __restrict__ out)
{
    __shared__ float tbl[TPB * NE];          // 32 KB static

    const int tid = threadIdx.x;
    const int n0  = blockIdx.x * TPB;        // first node of this block
    const int b0  = blockIdx.y * BB;         // first batch of this block

    // per-thread x base: batch stride is NODES*NI floats (compile-time constant)
    const float* xt = x + ((size_t)b0 * NODES + n0 + tid) * NI;

    // ---- kick off x prefetch for batches 0..PF-1 FIRST (overlaps table stage) ----
    float2 buf[PF][3];
    #pragma unroll
    for (int s = 0; s < PF; s++) {
        const float* p = xt + (size_t)s * (NODES * NI);
        buf[s][0] = *(const float2*)(p + 0);
        buf[s][1] = *(const float2*)(p + 2);
        buf[s][2] = *(const float2*)(p + 4);
    }

    // ---- stage this block's 32KB table chunk: coalesced LDG -> +2*row-rotated STS.64 ----
    {
        const float4* tg = (const float4*)(tables + (size_t)n0 * NE);
        #pragma unroll
        for (int j = 0; j < (TPB * NE / 4) / TPB; j++) {    // 16 float4 per thread
            int i = tid + j * TPB;                          // coalesced gmem index
            float4 v = tg[i];
            int r  = i >> 4;                                // dest row
            int c0 = (i & 15) * 4;                          // first word (even)
            float* row = tbl + r * NE;
            int w0 = (c0     + 2 * r) & (NE - 1);           // even -> 8B aligned
            int w1 = (c0 + 2 + 2 * r) & (NE - 1);
            *(float2*)(row + w0) = make_float2(v.x, v.y);
            *(float2*)(row + w1) = make_float2(v.z, v.w);
        }
    }
    __syncthreads();

    // ---- per-node packed quad coefficients over bits 0,1 (pairing = bit 5) ----
    // quad m covers entries 4m..4m+3 (lane lo) and 4m+32..4m+35 (lane hi):
    //   val = a + x0*b + x1*c + x0*x1*d
    u64 Aq[8], Bq[8], Cq[8], Dq[8];
    {
        const float* tr = tbl + (size_t)tid * NE;
        const int rot = (2 * tid) & (NE - 1);               // even: float2 pairs intact
        #pragma unroll
        for (int m = 0; m < 8; m++) {
            float2 l01 = *(const float2*)(tr + ((4*m      + rot) & (NE - 1)));
            float2 l23 = *(const float2*)(tr + ((4*m + 2  + rot) & (NE - 1)));
            float2 h01 = *(const float2*)(tr + ((4*m + 32 + rot) & (NE - 1)));
            float2 h23 = *(const float2*)(tr + ((4*m + 34 + rot) & (NE - 1)));
            float lb = l01.y - l01.x, hb = h01.y - h01.x;
            Aq[m] = pk2(l01.x, h01.x);
            Bq[m] = pk2(lb, hb);
            Cq[m] = pk2(l23.x - l01.x, h23.x - h01.x);
            Dq[m] = pk2((l23.y - l23.x) - lb, (h23.y - h23.x) - hb);
        }
    }

    float* op = out + (size_t)b0 * NODES + n0 + tid;

    // ---- mainloop: fully unrolled; all addressing base + compile-time immediate ----
    #pragma unroll
    for (int bb = 0; bb < BB; bb++) {
        const int s = bb % PF;
        float2 q0 = buf[s][0];
        float2 q1 = buf[s][1];
        float2 q2 = buf[s][2];

        if (bb + PF < BB) {                                 // refill slot for batch bb+PF
            const float* p = xt + (size_t)(bb + PF) * (NODES * NI);
            buf[s][0] = *(const float2*)(p + 0);
            buf[s][1] = *(const float2*)(p + 2);
            buf[s][2] = *(const float2*)(p + 4);
        }

        float c0 = __saturatef(q0.x), c1 = __saturatef(q0.y);
        float c2 = __saturatef(q1.x), c3 = __saturatef(q1.y);
        float c4 = __saturatef(q2.x), c5 = __saturatef(q2.y);
        float c01 = c0 * c1;
        u64 x0  = pk2(c0,  c0), x1 = pk2(c1, c1), x01 = pk2(c01, c01);
        u64 x2  = pk2(c2,  c2), x3 = pk2(c3, c3), x4  = pk2(c4, c4);

        // bits 0,1: 3 FFMA2 per quad, 8 independent chains
        u64 W[8];
        #pragma unroll
        for (int m = 0; m < 8; m++)
            W[m] = fma2(x01, Dq[m], fma2(x1, Cq[m], fma2(x0, Bq[m], Aq[m])));

        // bits 2..4: packed difference-form lerps
        #pragma unroll
        for (int m = 0; m < 4; m++) W[m] = fma2(x2, sub2(W[2*m+1], W[2*m]), W[2*m]);
        #pragma unroll
        for (int m = 0; m < 2; m++) W[m] = fma2(x3, sub2(W[2*m+1], W[2*m]), W[2*m]);
        W[0] = fma2(x4, sub2(W[1], W[0]), W[0]);

        // bit 5: scalar difference-form lerp across the packed halves
        float lo, hi; upk2(W[0], lo, hi);
        op[bb * NODES] = fmaf(c5, hi - lo, lo);             // immediate-offset STG
    }
}

extern "C" void kernel_launch(void* const* d_in, const int* in_sizes, int n_in,
                              void* d_out, int out_size)
{
    const float* x;
    const float* tables;
    if (in_sizes[0] == BATCH * NODES * NI) {
        x = (const float*)d_in[0]; tables = (const float*)d_in[1];
    } else {
        x = (const float*)d_in[1]; tables = (const float*)d_in[0];
    }
    dim3 grid(NODES / TPB, BATCH / BB);
    lut_kernel<<<grid, TPB>>>(x, tables, (float*)d_out);
}

// round 14
// speedup vs baseline: 1.7612x; 1.0060x over previous
#include <cuda_runtime.h>
#include <cstdint>

constexpr int BATCH = 128;
constexpr int NODES = 8192;
constexpr int NI    = 6;
constexpr int NE    = 64;
constexpr int BB    = 16;     // batches per thread
constexpr int TPB   = 128;
constexpr int PF    = 2;      // x prefetch depth (register double-buffer)
constexpr int XSTRIDE = NODES * NI;   // floats between consecutive batches

using u64 = unsigned long long;

__device__ __forceinline__ u64 pk2(float lo, float hi) {
    u64 r; asm("mov.b64 %0, {%1, %2};" : "=l"(r) : "f"(lo), "f"(hi)); return r;
}
__device__ __forceinline__ void upk2(u64 v, float& lo, float& hi) {
    asm("mov.b64 {%0, %1}, %2;" : "=f"(lo), "=f"(hi) : "l"(v));
}
__device__ __forceinline__ u64 fma2(u64 a, u64 b, u64 c) {
    u64 d; asm("fma.rn.f32x2 %0, %1, %2, %3;" : "=l"(d) : "l"(a), "l"(b), "l"(c)); return d;
}
__device__ __forceinline__ u64 sub2(u64 a, u64 b) {
    u64 d; asm("sub.rn.f32x2 %0, %1, %2;" : "=l"(d) : "l"(a), "l"(b)); return d;
}

// out[b,n] = 6-D multilinear interp of tables[n,:] at clip(x[b,n,:], 0, 1).
// Bits 0,1 folded into per-node quad coefficients (a + x0 b + x1 c + x0x1 d),
// bits 2..4 packed difference-form lerps, bit 5 packed across f32x2 lanes.
// x: coalesced LDG with a 2-slot register double-buffer; mainloop is rolled
// (unroll 2) with pointer increments to keep the live set under the 128-reg
// occ-4 cap (R10 fully-unrolled version spilled: regs=128, L1=24%).
__global__ void __launch_bounds__(TPB, 4)
lut_kernel(const float* __restrict__ x,
           const float* __restrict__ tables,
           float* __restrict__ out)
{
    __shared__ float tbl[TPB * NE];          // 32 KB static

    const int tid = threadIdx.x;
    const int n0  = blockIdx.x * TPB;        // first node of this block
    const int b0  = blockIdx.y * BB;         // first batch of this block

    const float* xt = x + ((size_t)b0 * NODES + n0 + tid) * NI;

    // ---- kick off x prefetch for batches 0..PF-1 FIRST (overlaps table stage) ----
    float2 buf[PF][3];
    #pragma unroll
    for (int s = 0; s < PF; s++) {
        const float* p = xt + (size_t)s * XSTRIDE;
        buf[s][0] = *(const float2*)(p + 0);
        buf[s][1] = *(const float2*)(p + 2);
        buf[s][2] = *(const float2*)(p + 4);
    }

    // ---- stage this block's 32KB table chunk: coalesced LDG -> +2*row-rotated STS.64 ----
    {
        const float4* tg = (const float4*)(tables + (size_t)n0 * NE);
        #pragma unroll
        for (int j = 0; j < (TPB * NE / 4) / TPB; j++) {    // 16 float4 per thread
            int i = tid + j * TPB;                          // coalesced gmem index
            float4 v = tg[i];
            int r  = i >> 4;                                // dest row
            int c0 = (i & 15) * 4;                          // first word (even)
            float* row = tbl + r * NE;
            int w0 = (c0     + 2 * r) & (NE - 1);           // even -> 8B aligned
            int w1 = (c0 + 2 + 2 * r) & (NE - 1);
            *(float2*)(row + w0) = make_float2(v.x, v.y);
            *(float2*)(row + w1) = make_float2(v.z, v.w);
        }
    }
    __syncthreads();

    // ---- per-node packed quad coefficients over bits 0,1 (pairing = bit 5) ----
    // quad m covers entries 4m..4m+3 (lane lo) and 4m+32..4m+35 (lane hi):
    //   val = a + x0*b + x1*c + x0*x1*d
    u64 Aq[8], Bq[8], Cq[8], Dq[8];
    {
        const float* tr = tbl + (size_t)tid * NE;
        const int rot = (2 * tid) & (NE - 1);               // even: float2 pairs intact
        #pragma unroll
        for (int m = 0; m < 8; m++) {
            float2 l01 = *(const float2*)(tr + ((4*m      + rot) & (NE - 1)));
            float2 l23 = *(const float2*)(tr + ((4*m + 2  + rot) & (NE - 1)));
            float2 h01 = *(const float2*)(tr + ((4*m + 32 + rot) & (NE - 1)));
            float2 h23 = *(const float2*)(tr + ((4*m + 34 + rot) & (NE - 1)));
            float lb = l01.y - l01.x, hb = h01.y - h01.x;
            Aq[m] = pk2(l01.x, h01.x);
            Bq[m] = pk2(lb, hb);
            Cq[m] = pk2(l23.x - l01.x, h23.x - h01.x);
            Dq[m] = pk2((l23.y - l23.x) - lb, (h23.y - h23.x) - hb);
        }
    }

    // ---- fold body (shared by mainloop and epilogue) ----
    auto fold = [&](float2 q0, float2 q1, float2 q2) -> float {
        float c0 = __saturatef(q0.x), c1 = __saturatef(q0.y);
        float c2 = __saturatef(q1.x), c3 = __saturatef(q1.y);
        float c4 = __saturatef(q2.x), c5 = __saturatef(q2.y);
        float c01 = c0 * c1;
        u64 x0  = pk2(c0,  c0), x1 = pk2(c1, c1), x01 = pk2(c01, c01);
        u64 x2  = pk2(c2,  c2), x3 = pk2(c3, c3), x4  = pk2(c4, c4);

        u64 W[8];
        #pragma unroll
        for (int m = 0; m < 8; m++)
            W[m] = fma2(x01, Dq[m], fma2(x1, Cq[m], fma2(x0, Bq[m], Aq[m])));
        #pragma unroll
        for (int m = 0; m < 4; m++) W[m] = fma2(x2, sub2(W[2*m+1], W[2*m]), W[2*m]);
        #pragma unroll
        for (int m = 0; m < 2; m++) W[m] = fma2(x3, sub2(W[2*m+1], W[2*m]), W[2*m]);
        W[0] = fma2(x4, sub2(W[1], W[0]), W[0]);

        float lo, hi; upk2(W[0], lo, hi);
        return fmaf(c5, hi - lo, lo);
    };

    float*       op   = out + (size_t)b0 * NODES + n0 + tid;
    const float* xpre = xt + (size_t)PF * XSTRIDE;

    // ---- mainloop: rolled, unroll 2 (slot index static), pointer increments ----
    #pragma unroll 2
    for (int bb = 0; bb < BB - PF; bb++) {
        const int s = bb & 1;
        float2 q0 = buf[s][0];
        float2 q1 = buf[s][1];
        float2 q2 = buf[s][2];

        buf[s][0] = *(const float2*)(xpre + 0);             // refill slot for bb+PF
        buf[s][1] = *(const float2*)(xpre + 2);
        buf[s][2] = *(const float2*)(xpre + 4);
        xpre += XSTRIDE;

        *op = fold(q0, q1, q2);
        op += NODES;
    }

    // ---- epilogue: last PF batches, no refill ----
    #pragma unroll
    for (int bb = BB - PF; bb < BB; bb++) {
        const int s = bb & 1;
        *op = fold(buf[s][0], buf[s][1], buf[s][2]);
        op += NODES;
    }
}

extern "C" void kernel_launch(void* const* d_in, const int* in_sizes, int n_in,
                              void* d_out, int out_size)
{
    const float* x;
    const float* tables;
    if (in_sizes[0] == BATCH * NODES * NI) {
        x = (const float*)d_in[0]; tables = (const float*)d_in[1];
    } else {
        x = (const float*)d_in[1]; tables = (const float*)d_in[0];
    }
    dim3 grid(NODES / TPB, BATCH / BB);
    lut_kernel<<<grid, TPB>>>(x, tables, (float*)d_out);
}